// round 12
// baseline (speedup 1.0000x reference)
#include <cuda_runtime.h>
#include <cuda_bf16.h>
#include <math.h>
#include <stdint.h>

typedef __nv_bfloat16 bf16;

#define D_  1024
#define S_  1024
#define B_  2
#define H_  16
#define DH_ 64
#define FF_ 4096
#define V_  32000
#define L_  12
#define ROWS_ (B_*S_)   // 2048
#define KA_D  3072      // 3*D
#define KA_FF 12288     // 3*FF
#define KA_DH 192       // 3*DH

// ======================= scratch (device globals) ===========================
__device__ __align__(256) float g_h  [ROWS_*D_];
__device__ __align__(256) float g_ctx[ROWS_*D_];
__device__ __align__(256) float g_sc [(size_t)B_*H_*S_*S_];

__device__ __align__(256) bf16 g_aa [(size_t)ROWS_*KA_D];            // A-layout acts
__device__ __align__(256) bf16 g_qa [(size_t)B_*H_*S_*KA_DH];        // Q aug per head
__device__ __align__(256) bf16 g_ka [(size_t)B_*H_*S_*KA_DH];        // K aug per head
__device__ __align__(256) bf16 g_va [(size_t)B_*H_*DH_*KA_D];        // V^T aug
__device__ __align__(256) bf16 g_ffa[(size_t)ROWS_*KA_FF];           // gelu out aug
__device__ __align__(256) bf16 g_pa [(size_t)B_*H_*S_*KA_D];         // probs aug

__device__ __align__(256) bf16 g_wq [(size_t)L_*D_*KA_D];
__device__ __align__(256) bf16 g_wk [(size_t)L_*D_*KA_D];
__device__ __align__(256) bf16 g_wv [(size_t)L_*D_*KA_D];
__device__ __align__(256) bf16 g_w1 [(size_t)L_*FF_*KA_D];
__device__ __align__(256) bf16 g_w2 [(size_t)L_*D_*KA_FF];
__device__ __align__(256) bf16 g_wlm[(size_t)V_*KA_D];

// ======================= helpers ============================================
__device__ __forceinline__ uint32_t smem_to_u32(const void* p) {
    uint32_t a;
    asm("{ .reg .u64 t; cvta.to.shared.u64 t, %1; cvt.u32.u64 %0, t; }"
        : "=r"(a) : "l"(p));
    return a;
}
__device__ __forceinline__ void cp16(bf16* s, const bf16* g) {
    uint32_t sa = smem_to_u32(s);
    asm volatile("cp.async.cg.shared.global [%0], [%1], 16;" :: "r"(sa), "l"(g));
}
#define CP_COMMIT() asm volatile("cp.async.commit_group;" ::: "memory")

#define LDSM4(R0,R1,R2,R3,ADDR) \
    asm volatile("ldmatrix.sync.aligned.m8n8.x4.shared.b16 {%0,%1,%2,%3}, [%4];" \
        : "=r"(R0), "=r"(R1), "=r"(R2), "=r"(R3) : "r"(ADDR))

#define MMA16816(C0,C1,C2,C3,A0,A1,A2,A3,B0,B1) \
    asm volatile("mma.sync.aligned.m16n8k16.row.col.f32.bf16.bf16.f32 " \
        "{%0,%1,%2,%3}, {%4,%5,%6,%7}, {%8,%9}, {%0,%1,%2,%3};" \
        : "+f"(C0), "+f"(C1), "+f"(C2), "+f"(C3) \
        : "r"(A0), "r"(A1), "r"(A2), "r"(A3), "r"(B0), "r"(B1))

__device__ __forceinline__ void split2(float v, bf16& h, bf16& l) {
    h = __float2bfloat16(v);
    l = __float2bfloat16(v - __bfloat162float(h));
}

// ======================= epilogue functors ==================================
struct EpiF32 {      // fp32 out (+opt bias)
    float* C; const float* bias; int ldc;
    __device__ void operator()(int z, int r, int c, float v) const {
        if (bias) v += bias[c];
        C[(size_t)r*ldc + c] = v;
    }
};
struct EpiQKV {      // z=0: Q split, z=1: K split, z=2: V transpose-split
    const float *bq, *bk, *bv;
    __device__ void operator()(int z, int r, int c, float v) const {
        int hh = c >> 6, d = c & 63;
        int b = r >> 10, s = r & 1023;
        if (z == 0) {
            v += bq[c];
            size_t base = ((size_t)((b << 4) + hh) * S_ + s) * KA_DH + d;
            bf16 h, l; split2(v, h, l);
            g_qa[base] = h; g_qa[base + 64] = l; g_qa[base + 128] = h;
        } else if (z == 1) {
            v += bk[c];
            size_t base = ((size_t)((b << 4) + hh) * S_ + s) * KA_DH + d;
            bf16 h, l; split2(v, h, l);
            g_ka[base] = h; g_ka[base + 64] = h; g_ka[base + 128] = l;
        } else {
            v += bv[c];
            size_t o = ((size_t)((b << 4) + hh) * DH_ + d) * KA_D + s;
            bf16 h, l; split2(v, h, l);
            g_va[o] = h; g_va[o + S_] = h; g_va[o + 2*S_] = l;
        }
    }
};
struct EpiGelu {     // FF1: bias + gelu + split -> g_ffa (h,l,h)
    const float* bias;
    __device__ void operator()(int z, int r, int c, float v) const {
        v += bias[c];
        v = v * 0.5f * (1.0f + erff(v * 0.70710678118654752f));
        bf16 h, l; split2(v, h, l);
        size_t base = (size_t)r * KA_FF + c;
        g_ffa[base] = h; g_ffa[base + FF_] = l; g_ffa[base + 2*FF_] = h;
    }
};
struct EpiScore {    // scores: scale + mask bias -> g_sc fp32
    const float* mask;
    __device__ void operator()(int z, int r, int c, float v) const {
        int b = z >> 4;
        g_sc[(size_t)z*S_*S_ + (size_t)r*S_ + c] =
            v * 0.125f + (1.0f - mask[b*S_ + c]) * -10000.0f;
    }
};
struct EpiCtx {      // ctx: fp32 -> g_ctx at head cols
    __device__ void operator()(int z, int r, int c, float v) const {
        int b = z >> 4, hh = z & 15;
        g_ctx[((size_t)(b * S_) + r) * D_ + hh*64 + c] = v;
    }
};

// ======================= pipelined mma.sync GEMM core =======================
// 128-thread CTA, 4 warps in 2x2, warp tile 64 x BN/2, BK=32, NSTG stages.
template<int BN>
__device__ __forceinline__ void load_stage(const bf16* Ap, const bf16* Bp,
                                           bf16* As, bf16* Bs,
                                           int st, int k0, int K, int tid)
{
    constexpr int LDS = 40, ASZ = 128*LDS, BSZ = BN*LDS;
#pragma unroll
    for (int i = 0; i < 4; i++) {
        int ch = tid + i*128;
        int row = ch >> 2, c = ch & 3;
        cp16(As + st*ASZ + row*LDS + c*8, Ap + (size_t)row*K + k0 + c*8);
    }
#pragma unroll
    for (int i = 0; i < BN/32; i++) {
        int ch = tid + i*128;
        int row = ch >> 2, c = ch & 3;
        cp16(Bs + st*BSZ + row*LDS + c*8, Bp + (size_t)row*K + k0 + c*8);
    }
    CP_COMMIT();
}

template<int BN, int NSTG, class Epi>
__device__ __forceinline__ void gemm_core(const bf16* __restrict__ Ap,
                                          const bf16* __restrict__ Bp,
                                          int K, int z, int by, int bx,
                                          const Epi& epi)
{
    constexpr int NT  = BN / 16;       // n8-tiles per warp (warp tile 64 x BN/2)
    constexpr int LDS = 40;
    constexpr int ASZ = 128*LDS, BSZ = BN*LDS;
    extern __shared__ bf16 sm[];
    bf16* As = sm;
    bf16* Bs = sm + NSTG*ASZ;

    const int tid = threadIdx.x, lane = tid & 31, wid = tid >> 5;
    const int wr = wid >> 1, wc = wid & 1;

    float acc[4][NT][4];
#pragma unroll
    for (int i = 0; i < 4; i++)
#pragma unroll
        for (int j = 0; j < NT; j++)
#pragma unroll
            for (int k = 0; k < 4; k++) acc[i][j][k] = 0.f;

    const uint32_t smBase = smem_to_u32(sm);
    const uint32_t aOff = (((lane & 15)*LDS) + ((lane >> 4) & 1)*8) * 2;
    const uint32_t bOff = ((((lane & 7) + ((lane >> 4) << 3))*LDS) + ((lane >> 3) & 1)*8) * 2;

    const int NK = K >> 5;
#pragma unroll
    for (int p = 0; p < NSTG-1; p++)
        load_stage<BN>(Ap, Bp, As, Bs, p, p*32, K, tid);

    int st = 0, nst = (NSTG-1 < NSTG) ? NSTG-1 : 0;
    for (int it = 0; it < NK; it++) {
        const int rem = NK - 1 - it;
        if (NSTG == 4) {
            if (rem >= 2)      asm volatile("cp.async.wait_group 2;" ::: "memory");
            else if (rem == 1) asm volatile("cp.async.wait_group 1;" ::: "memory");
            else               asm volatile("cp.async.wait_group 0;" ::: "memory");
        } else { // NSTG == 3
            if (rem >= 1)      asm volatile("cp.async.wait_group 1;" ::: "memory");
            else               asm volatile("cp.async.wait_group 0;" ::: "memory");
        }
        __syncthreads();
        const int nx = it + NSTG - 1;
        if (nx < NK) {
            load_stage<BN>(Ap, Bp, As, Bs, nst, nx << 5, K, tid);
        }

        const uint32_t aS = smBase + (uint32_t)(st*ASZ + wr*64*LDS)*2 + aOff;
        const uint32_t bS = smBase + (uint32_t)(NSTG*ASZ + st*BSZ + wc*(BN/2)*LDS)*2 + bOff;
#pragma unroll
        for (int kk = 0; kk < 2; kk++) {
            uint32_t af[4][4];
#pragma unroll
            for (int mt = 0; mt < 4; mt++)
                LDSM4(af[mt][0], af[mt][1], af[mt][2], af[mt][3],
                      aS + (uint32_t)(mt*16*LDS + kk*16)*2);
            uint32_t bfr[NT][2];
#pragma unroll
            for (int np = 0; np < NT/2; np++) {
                uint32_t r0, r1, r2, r3;
                LDSM4(r0, r1, r2, r3, bS + (uint32_t)(np*16*LDS + kk*16)*2);
                bfr[2*np][0] = r0; bfr[2*np][1] = r1;
                bfr[2*np+1][0] = r2; bfr[2*np+1][1] = r3;
            }
#pragma unroll
            for (int mt = 0; mt < 4; mt++)
#pragma unroll
                for (int nt = 0; nt < NT; nt++)
                    MMA16816(acc[mt][nt][0], acc[mt][nt][1], acc[mt][nt][2], acc[mt][nt][3],
                             af[mt][0], af[mt][1], af[mt][2], af[mt][3],
                             bfr[nt][0], bfr[nt][1]);
        }
        st = (st + 1 == NSTG) ? 0 : st + 1;
        nst = (nst + 1 == NSTG) ? 0 : nst + 1;
    }

    const int lr = lane >> 2, lc = (lane & 3) << 1;
#pragma unroll
    for (int mt = 0; mt < 4; mt++)
#pragma unroll
        for (int nt = 0; nt < NT; nt++) {
            int r0 = by*128 + wr*64 + mt*16 + lr;
            int c0 = bx*BN + wc*(BN/2) + nt*8 + lc;
            epi(z, r0,     c0,     acc[mt][nt][0]);
            epi(z, r0,     c0 + 1, acc[mt][nt][1]);
            epi(z, r0 + 8, c0,     acc[mt][nt][2]);
            epi(z, r0 + 8, c0 + 1, acc[mt][nt][3]);
        }
}

template<int BN, int NSTG, int OCC, class Epi>
__global__ __launch_bounds__(128, OCC)
void gemm_k(const bf16* __restrict__ A, const bf16* __restrict__ B, int K,
            size_t sA, size_t sB, Epi epi)
{
    const int z = blockIdx.z;
    const bf16* Ap = A + (size_t)z*sA + (size_t)blockIdx.y * 128 * K;
    const bf16* Bp = B + (size_t)z*sB + (size_t)blockIdx.x * BN  * K;
    gemm_core<BN, NSTG, Epi>(Ap, Bp, K, z, blockIdx.y, blockIdx.x, epi);
}

__global__ __launch_bounds__(128, 3)
void qkv_k(const bf16* __restrict__ A,
           const bf16* __restrict__ Wq, const bf16* __restrict__ Wk,
           const bf16* __restrict__ Wv, EpiQKV epi)
{
    const int z = blockIdx.z;
    const bf16* W = (z == 0) ? Wq : (z == 1) ? Wk : Wv;
    const bf16* Ap = A + (size_t)blockIdx.y * 128 * KA_D;
    const bf16* Bp = W + (size_t)blockIdx.x * 128 * KA_D;
    gemm_core<128, 3, EpiQKV>(Ap, Bp, KA_D, z, blockIdx.y, blockIdx.x, epi);
}

// ======================= weight transpose+split (B-layout) ==================
// W[K,N] fp32 -> out[N, 3K] bf16: [Wh | Wh | Wl]
__device__ __forceinline__ void wsplit_body(const float* __restrict__ W,
        bf16* __restrict__ out, int K, int N, int zmat, int bx, int by, int tid)
{
    __shared__ float t[32][33];
    const size_t mat  = (size_t)zmat * K * N;
    const size_t mato = (size_t)zmat * K * N * 3;
    const int n0 = bx*32, k0 = by*32;
    const int tx = tid & 31, ty = tid >> 5;
#pragma unroll
    for (int i = 0; i < 4; i++) {
        int k = k0 + ty*4 + i;
        t[ty*4+i][tx] = W[mat + (size_t)k*N + n0 + tx];
    }
    __syncthreads();
#pragma unroll
    for (int i = 0; i < 4; i++) {
        int n = n0 + ty*4 + i;
        float v = t[tx][ty*4+i];
        bf16 h, l; split2(v, h, l);
        size_t o = mato + (size_t)n*3*K + k0 + tx;
        out[o] = h; out[o + K] = h; out[o + 2*K] = l;
    }
}

__global__ __launch_bounds__(256) void wsplit_kernel(const float* __restrict__ W,
        bf16* __restrict__ out, int K, int N)
{
    wsplit_body(W, out, K, N, blockIdx.z, blockIdx.x, blockIdx.y, threadIdx.x);
}

// all 3 QKV weights in one launch: z = w*L + l, w in {0,1,2}
__global__ __launch_bounds__(256) void wsplit_qkv_kernel(
        const float* __restrict__ Wq, const float* __restrict__ Wk,
        const float* __restrict__ Wv,
        bf16* __restrict__ oq, bf16* __restrict__ ok, bf16* __restrict__ ov)
{
    const int w = blockIdx.z / L_, l = blockIdx.z % L_;
    const float* W = (w == 0) ? Wq : (w == 1) ? Wk : Wv;
    bf16* out = (w == 0) ? oq : (w == 1) ? ok : ov;
    wsplit_body(W, out, D_, D_, l, blockIdx.x, blockIdx.y, threadIdx.x);
}

// ======================= softmax (fp32 in -> aug bf16 out) ==================
__global__ __launch_bounds__(256) void softmax_split_kernel()
{
    const size_t base = (size_t)blockIdx.x * S_;
    const int tid = threadIdx.x;
    float x[4];
    float mx = -1e30f;
#pragma unroll
    for (int i = 0; i < 4; i++) {
        x[i] = g_sc[base + tid + i*256];
        mx = fmaxf(mx, x[i]);
    }
#pragma unroll
    for (int off = 16; off; off >>= 1)
        mx = fmaxf(mx, __shfl_xor_sync(0xffffffffu, mx, off));
    __shared__ float red[8];
    if ((tid & 31) == 0) red[tid >> 5] = mx;
    __syncthreads();
    if (tid == 0) {
        float v = red[0];
#pragma unroll
        for (int i = 1; i < 8; i++) v = fmaxf(v, red[i]);
        red[0] = v;
    }
    __syncthreads();
    mx = red[0];
    __syncthreads();
    float sum = 0.f;
#pragma unroll
    for (int i = 0; i < 4; i++) { x[i] = expf(x[i] - mx); sum += x[i]; }
#pragma unroll
    for (int off = 16; off; off >>= 1)
        sum += __shfl_xor_sync(0xffffffffu, sum, off);
    if ((tid & 31) == 0) red[tid >> 5] = sum;
    __syncthreads();
    if (tid == 0) {
        float v = 0.f;
#pragma unroll
        for (int i = 0; i < 8; i++) v += red[i];
        red[0] = 1.0f / v;
    }
    __syncthreads();
    const float inv = red[0];
    const size_t ob = (size_t)blockIdx.x * KA_D;
#pragma unroll
    for (int i = 0; i < 4; i++) {
        int idx = tid + i*256;
        float p = x[i] * inv;
        bf16 h, l; split2(p, h, l);
        g_pa[ob + idx] = h; g_pa[ob + S_ + idx] = l; g_pa[ob + 2*S_ + idx] = h;
    }
}

// ======================= LayerNorm (fp32 h + aug split out) =================
__device__ __forceinline__ void ln_stats(float s, float ss, float& mean, float& rstd)
{
#pragma unroll
    for (int off = 16; off; off >>= 1) {
        s  += __shfl_xor_sync(0xffffffffu, s,  off);
        ss += __shfl_xor_sync(0xffffffffu, ss, off);
    }
    __shared__ float rs[8], rss[8];
    const int w = threadIdx.x >> 5;
    if ((threadIdx.x & 31) == 0) { rs[w] = s; rss[w] = ss; }
    __syncthreads();
    if (threadIdx.x == 0) {
        float a = 0.f, bb = 0.f;
#pragma unroll
        for (int i = 0; i < 8; i++) { a += rs[i]; bb += rss[i]; }
        float mu  = a * (1.0f / 1024.0f);
        float var = bb * (1.0f / 1024.0f) - mu * mu;
        rs[0]  = mu;
        rss[0] = rsqrtf(var + 1e-5f);
    }
    __syncthreads();
    mean = rs[0];
    rstd = rss[0];
}

__device__ __forceinline__ void write_act(size_t row, int idx, float y)
{
    g_h[row*D_ + idx] = y;
    bf16 h, l; split2(y, h, l);
    size_t b3 = row*KA_D + idx;
    g_aa[b3] = h; g_aa[b3 + D_] = l; g_aa[b3 + 2*D_] = h;
}

__global__ __launch_bounds__(256) void embed_ln_kernel(const int* __restrict__ ids,
                                                       const float* __restrict__ tok,
                                                       const float* __restrict__ pos,
                                                       const float* __restrict__ g,
                                                       const float* __restrict__ be)
{
    const int row  = blockIdx.x;
    const int spos = row & (S_ - 1);
    const size_t tbase = (size_t)ids[row] * D_;
    const size_t pbase = (size_t)spos * D_;
    float x[4]; float s = 0.f, ss = 0.f;
#pragma unroll
    for (int i = 0; i < 4; i++) {
        int idx = threadIdx.x + i*256;
        x[i] = tok[tbase + idx] + pos[pbase + idx];
        s += x[i]; ss += x[i]*x[i];
    }
    float mean, rstd;
    ln_stats(s, ss, mean, rstd);
#pragma unroll
    for (int i = 0; i < 4; i++) {
        int idx = threadIdx.x + i*256;
        write_act(row, idx, (x[i] - mean) * rstd * g[idx] + be[idx]);
    }
}

__global__ __launch_bounds__(256) void add_ln_kernel(const float* __restrict__ g,
                                                     const float* __restrict__ be)
{
    const size_t base = (size_t)blockIdx.x * D_;
    float x[4]; float s = 0.f, ss = 0.f;
#pragma unroll
    for (int i = 0; i < 4; i++) {
        int idx = threadIdx.x + i*256;
        x[i] = g_h[base + idx] + g_ctx[base + idx];
        s += x[i]; ss += x[i]*x[i];
    }
    float mean, rstd;
    ln_stats(s, ss, mean, rstd);
#pragma unroll
    for (int i = 0; i < 4; i++) {
        int idx = threadIdx.x + i*256;
        write_act(blockIdx.x, idx, (x[i] - mean) * rstd * g[idx] + be[idx]);
    }
}

// ======================= driver =============================================
#define SM3_128 (3*(128*40 + 128*40)*2)   // 61440  (3-stage, occ 3)
#define SM4_128 (4*(128*40 + 128*40)*2)   // 81920  (4-stage, occ 2)
#define SM3_64  (3*(128*40 +  64*40)*2)   // 46080
#define SM4_64  (4*(128*40 +  64*40)*2)   // 61440

extern "C" void kernel_launch(void* const* d_in, const int* in_sizes, int n_in,
                              void* d_out, int out_size)
{
    (void)in_sizes; (void)n_in; (void)out_size;
    const int*   ids  = (const int*)  d_in[0];
    const float* mask = (const float*)d_in[1];
    const float* tok  = (const float*)d_in[2];
    const float* pos  = (const float*)d_in[3];
    const float* ln0g = (const float*)d_in[4];
    const float* ln0b = (const float*)d_in[5];
    const float* Wq   = (const float*)d_in[6];
    const float* bq   = (const float*)d_in[7];
    const float* Wk   = (const float*)d_in[8];
    const float* bk   = (const float*)d_in[9];
    const float* Wv   = (const float*)d_in[10];
    const float* bv   = (const float*)d_in[11];
    const float* ln1g = (const float*)d_in[12];
    const float* ln1b = (const float*)d_in[13];
    const float* W1   = (const float*)d_in[14];
    const float* b1   = (const float*)d_in[15];
    const float* W2   = (const float*)d_in[16];
    const float* b2   = (const float*)d_in[17];
    const float* ln2g = (const float*)d_in[18];
    const float* ln2b = (const float*)d_in[19];
    const float* Wlm  = (const float*)d_in[20];

    cudaFuncSetAttribute(qkv_k, cudaFuncAttributeMaxDynamicSharedMemorySize, SM3_128);
    cudaFuncSetAttribute(gemm_k<128, 4, 2, EpiScore>, cudaFuncAttributeMaxDynamicSharedMemorySize, SM4_128);
    cudaFuncSetAttribute(gemm_k<128, 3, 3, EpiGelu>,  cudaFuncAttributeMaxDynamicSharedMemorySize, SM3_128);
    cudaFuncSetAttribute(gemm_k<128, 3, 3, EpiF32>,   cudaFuncAttributeMaxDynamicSharedMemorySize, SM3_128);
    cudaFuncSetAttribute(gemm_k<64,  3, 3, EpiF32>,   cudaFuncAttributeMaxDynamicSharedMemorySize, SM3_64);
    cudaFuncSetAttribute(gemm_k<64,  4, 2, EpiCtx>,   cudaFuncAttributeMaxDynamicSharedMemorySize, SM4_64);

    bf16 *wq, *wk, *wv, *w1, *w2, *wlm, *aa, *qa, *ka, *va, *ffa, *pa;
    float *ctxp;
    cudaGetSymbolAddress((void**)&wq,  g_wq);
    cudaGetSymbolAddress((void**)&wk,  g_wk);
    cudaGetSymbolAddress((void**)&wv,  g_wv);
    cudaGetSymbolAddress((void**)&w1,  g_w1);
    cudaGetSymbolAddress((void**)&w2,  g_w2);
    cudaGetSymbolAddress((void**)&wlm, g_wlm);
    cudaGetSymbolAddress((void**)&aa,  g_aa);
    cudaGetSymbolAddress((void**)&qa,  g_qa);
    cudaGetSymbolAddress((void**)&ka,  g_ka);
    cudaGetSymbolAddress((void**)&va,  g_va);
    cudaGetSymbolAddress((void**)&ffa, g_ffa);
    cudaGetSymbolAddress((void**)&pa,  g_pa);
    cudaGetSymbolAddress((void**)&ctxp, g_ctx);

    // weight conversion (4 launches), then embed (5th), so the 6th launch the
    // profiler lands on (-s 5 -c 1) is the first QKV GEMM.
    wsplit_qkv_kernel<<<dim3(D_/32, D_/32, 3*L_), 256>>>(Wq, Wk, Wv, wq, wk, wv);
    wsplit_kernel<<<dim3(FF_/32, D_/32,  L_), 256>>>(W1,  w1,  D_,  FF_);
    wsplit_kernel<<<dim3(D_/32,  FF_/32, L_), 256>>>(W2,  w2,  FF_, D_);
    wsplit_kernel<<<dim3(V_/32,  D_/32,  1 ), 256>>>(Wlm, wlm, D_,  V_);

    embed_ln_kernel<<<ROWS_, 256>>>(ids, tok, pos, ln0g, ln0b);

    const size_t WDD = (size_t)D_*KA_D;
    const size_t W1S = (size_t)FF_*KA_D;
    const size_t W2S = (size_t)D_*KA_FF;

    for (int l = 0; l < L_; l++) {
        qkv_k<<<dim3(D_/128, ROWS_/128, 3), 128, SM3_128>>>(
            aa, wq + l*WDD, wk + l*WDD, wv + l*WDD,
            EpiQKV{bq + (size_t)l*D_, bk + (size_t)l*D_, bv + (size_t)l*D_});

        gemm_k<128, 4, 2, EpiScore><<<dim3(S_/128, S_/128, B_*H_), 128, SM4_128>>>(
            qa, ka, KA_DH, (size_t)S_*KA_DH, (size_t)S_*KA_DH, EpiScore{mask});
        softmax_split_kernel<<<B_*H_*S_, 256>>>();
        gemm_k<64, 4, 2, EpiCtx><<<dim3(1, S_/128, B_*H_), 128, SM4_64>>>(
            pa, va, KA_D, (size_t)S_*KA_D, (size_t)DH_*KA_D, EpiCtx{});

        add_ln_kernel<<<ROWS_, 256>>>(ln1g + (size_t)l*D_, ln1b + (size_t)l*D_);

        gemm_k<128, 3, 3, EpiGelu><<<dim3(FF_/128, ROWS_/128, 1), 128, SM3_128>>>(
            aa, w1 + l*W1S, KA_D, 0, 0, EpiGelu{b1 + (size_t)l*FF_});
        gemm_k<64, 3, 3, EpiF32><<<dim3(D_/64, ROWS_/128, 1), 128, SM3_64>>>(
            ffa, w2 + l*W2S, KA_FF, 0, 0, EpiF32{ctxp, b2 + (size_t)l*D_, D_});

        add_ln_kernel<<<ROWS_, 256>>>(ln2g + (size_t)l*D_, ln2b + (size_t)l*D_);
    }

    gemm_k<128, 3, 3, EpiF32><<<dim3(V_/128, ROWS_/128, 1), 128, SM3_128>>>(
        aa, wlm, KA_D, 0, 0, EpiF32{(float*)d_out, nullptr, V_});
}

// round 14
// speedup vs baseline: 1.5913x; 1.5913x over previous
#include <cuda_runtime.h>
#include <cuda_bf16.h>
#include <math.h>
#include <stdint.h>

typedef __nv_bfloat16 bf16;

#define D_  1024
#define S_  1024
#define B_  2
#define H_  16
#define DH_ 64
#define FF_ 4096
#define V_  32000
#define L_  12
#define ROWS_ (B_*S_)   // 2048
#define KA_D  3072      // 3*D
#define KA_FF 12288     // 3*FF
#define KA_DH 192       // 3*DH

// ======================= scratch (device globals) ===========================
__device__ __align__(256) float g_h  [ROWS_*D_];
__device__ __align__(256) float g_ctx[ROWS_*D_];
__device__ __align__(256) float g_sc [(size_t)B_*H_*S_*S_];

__device__ __align__(256) bf16 g_aa [(size_t)ROWS_*KA_D];            // A-layout acts
__device__ __align__(256) bf16 g_qa [(size_t)B_*H_*S_*KA_DH];        // Q aug per head
__device__ __align__(256) bf16 g_ka [(size_t)B_*H_*S_*KA_DH];        // K aug per head
__device__ __align__(256) bf16 g_va [(size_t)B_*H_*DH_*KA_D];        // V^T aug
__device__ __align__(256) bf16 g_ffa[(size_t)ROWS_*KA_FF];           // gelu out aug
__device__ __align__(256) bf16 g_pa [(size_t)B_*H_*S_*KA_D];         // probs aug

__device__ __align__(256) bf16 g_wq [(size_t)L_*D_*KA_D];
__device__ __align__(256) bf16 g_wk [(size_t)L_*D_*KA_D];
__device__ __align__(256) bf16 g_wv [(size_t)L_*D_*KA_D];
__device__ __align__(256) bf16 g_w1 [(size_t)L_*FF_*KA_D];
__device__ __align__(256) bf16 g_w2 [(size_t)L_*D_*KA_FF];
__device__ __align__(256) bf16 g_wlm[(size_t)V_*KA_D];

// ======================= helpers ============================================
__device__ __forceinline__ uint32_t smem_to_u32(const void* p) {
    uint32_t a;
    asm("{ .reg .u64 t; cvta.to.shared.u64 t, %1; cvt.u32.u64 %0, t; }"
        : "=r"(a) : "l"(p));
    return a;
}
__device__ __forceinline__ void cp16(bf16* s, const bf16* g) {
    uint32_t sa = smem_to_u32(s);
    asm volatile("cp.async.cg.shared.global [%0], [%1], 16;" :: "r"(sa), "l"(g));
}
#define CP_COMMIT() asm volatile("cp.async.commit_group;" ::: "memory")

#define LDSM4(R0,R1,R2,R3,ADDR) \
    asm volatile("ldmatrix.sync.aligned.m8n8.x4.shared.b16 {%0,%1,%2,%3}, [%4];" \
        : "=r"(R0), "=r"(R1), "=r"(R2), "=r"(R3) : "r"(ADDR))

#define MMA16816(C0,C1,C2,C3,A0,A1,A2,A3,B0,B1) \
    asm volatile("mma.sync.aligned.m16n8k16.row.col.f32.bf16.bf16.f32 " \
        "{%0,%1,%2,%3}, {%4,%5,%6,%7}, {%8,%9}, {%0,%1,%2,%3};" \
        : "+f"(C0), "+f"(C1), "+f"(C2), "+f"(C3) \
        : "r"(A0), "r"(A1), "r"(A2), "r"(A3), "r"(B0), "r"(B1))

__device__ __forceinline__ void split2(float v, bf16& h, bf16& l) {
    h = __float2bfloat16(v);
    l = __float2bfloat16(v - __bfloat162float(h));
}

// ======================= epilogue functors ==================================
struct EpiF32 {      // fp32 out (+opt bias)
    float* C; const float* bias; int ldc;
    __device__ void operator()(int z, int r, int c, float v) const {
        if (bias) v += bias[c];
        C[(size_t)r*ldc + c] = v;
    }
};
struct EpiQKV {      // z=0: Q split, z=1: K split, z=2: V transpose-split
    const float *bq, *bk, *bv;
    __device__ void operator()(int z, int r, int c, float v) const {
        int hh = c >> 6, d = c & 63;
        int b = r >> 10, s = r & 1023;
        if (z == 0) {
            v += bq[c];
            size_t base = ((size_t)((b << 4) + hh) * S_ + s) * KA_DH + d;
            bf16 h, l; split2(v, h, l);
            g_qa[base] = h; g_qa[base + 64] = l; g_qa[base + 128] = h;
        } else if (z == 1) {
            v += bk[c];
            size_t base = ((size_t)((b << 4) + hh) * S_ + s) * KA_DH + d;
            bf16 h, l; split2(v, h, l);
            g_ka[base] = h; g_ka[base + 64] = h; g_ka[base + 128] = l;
        } else {
            v += bv[c];
            size_t o = ((size_t)((b << 4) + hh) * DH_ + d) * KA_D + s;
            bf16 h, l; split2(v, h, l);
            g_va[o] = h; g_va[o + S_] = h; g_va[o + 2*S_] = l;
        }
    }
};
struct EpiGelu {     // FF1: bias + gelu + split -> g_ffa (h,l,h)
    const float* bias;
    __device__ void operator()(int z, int r, int c, float v) const {
        v += bias[c];
        v = v * 0.5f * (1.0f + erff(v * 0.70710678118654752f));
        bf16 h, l; split2(v, h, l);
        size_t base = (size_t)r * KA_FF + c;
        g_ffa[base] = h; g_ffa[base + FF_] = l; g_ffa[base + 2*FF_] = h;
    }
};
struct EpiScore {    // scores: scale + mask bias -> g_sc fp32
    const float* mask;
    __device__ void operator()(int z, int r, int c, float v) const {
        int b = z >> 4;
        g_sc[(size_t)z*S_*S_ + (size_t)r*S_ + c] =
            v * 0.125f + (1.0f - mask[b*S_ + c]) * -10000.0f;
    }
};
struct EpiCtx {      // ctx: fp32 -> g_ctx at head cols
    __device__ void operator()(int z, int r, int c, float v) const {
        int b = z >> 4, hh = z & 15;
        g_ctx[((size_t)(b * S_) + r) * D_ + hh*64 + c] = v;
    }
};

// ======================= pipelined mma.sync GEMM core =======================
// 128-thread CTA, 4 warps in 2x2, warp tile 64 x BN/2, BK=32, 4 stages.
template<int BN>
__device__ __forceinline__ void load_stage(const bf16* Ap, const bf16* Bp,
                                           bf16* As, bf16* Bs,
                                           int st, int k0, int K, int tid)
{
    constexpr int LDS = 40, ASZ = 128*LDS, BSZ = BN*LDS;
#pragma unroll
    for (int i = 0; i < 4; i++) {
        int ch = tid + i*128;
        int row = ch >> 2, c = ch & 3;
        cp16(As + st*ASZ + row*LDS + c*8, Ap + (size_t)row*K + k0 + c*8);
    }
#pragma unroll
    for (int i = 0; i < BN/32; i++) {
        int ch = tid + i*128;
        int row = ch >> 2, c = ch & 3;
        cp16(Bs + st*BSZ + row*LDS + c*8, Bp + (size_t)row*K + k0 + c*8);
    }
    CP_COMMIT();
}

template<int BN, class Epi>
__device__ __forceinline__ void gemm_core(const bf16* __restrict__ Ap,
                                          const bf16* __restrict__ Bp,
                                          int K, int z, int by, int bx,
                                          const Epi& epi)
{
    constexpr int NT  = BN / 16;       // n8-tiles per warp (warp tile 64 x BN/2)
    constexpr int LDS = 40;
    constexpr int ASZ = 128*LDS, BSZ = BN*LDS;
    constexpr int NSTG = 4;
    extern __shared__ bf16 sm[];
    bf16* As = sm;
    bf16* Bs = sm + NSTG*ASZ;

    const int tid = threadIdx.x, lane = tid & 31, wid = tid >> 5;
    const int wr = wid >> 1, wc = wid & 1;

    float acc[4][NT][4];
#pragma unroll
    for (int i = 0; i < 4; i++)
#pragma unroll
        for (int j = 0; j < NT; j++)
#pragma unroll
            for (int k = 0; k < 4; k++) acc[i][j][k] = 0.f;

    const uint32_t smBase = smem_to_u32(sm);
    const uint32_t aOff = (((lane & 15)*LDS) + ((lane >> 4) & 1)*8) * 2;
    const uint32_t bOff = ((((lane & 7) + ((lane >> 4) << 3))*LDS) + ((lane >> 3) & 1)*8) * 2;

    const int NK = K >> 5;
    load_stage<BN>(Ap, Bp, As, Bs, 0, 0,  K, tid);
    load_stage<BN>(Ap, Bp, As, Bs, 1, 32, K, tid);
    load_stage<BN>(Ap, Bp, As, Bs, 2, 64, K, tid);

    for (int it = 0; it < NK; it++) {
        const int rem = NK - 1 - it;
        if (rem >= 2)      asm volatile("cp.async.wait_group 2;" ::: "memory");
        else if (rem == 1) asm volatile("cp.async.wait_group 1;" ::: "memory");
        else               asm volatile("cp.async.wait_group 0;" ::: "memory");
        __syncthreads();
        const int nx = it + 3;
        if (nx < NK) load_stage<BN>(Ap, Bp, As, Bs, nx & 3, nx << 5, K, tid);

        const int st = it & 3;
        const uint32_t aS = smBase + (uint32_t)(st*ASZ + wr*64*LDS)*2 + aOff;
        const uint32_t bS = smBase + (uint32_t)(NSTG*ASZ + st*BSZ + wc*(BN/2)*LDS)*2 + bOff;
#pragma unroll
        for (int kk = 0; kk < 2; kk++) {
            uint32_t af[4][4];
#pragma unroll
            for (int mt = 0; mt < 4; mt++)
                LDSM4(af[mt][0], af[mt][1], af[mt][2], af[mt][3],
                      aS + (uint32_t)(mt*16*LDS + kk*16)*2);
            uint32_t bfr[NT][2];
#pragma unroll
            for (int np = 0; np < NT/2; np++) {
                uint32_t r0, r1, r2, r3;
                LDSM4(r0, r1, r2, r3, bS + (uint32_t)(np*16*LDS + kk*16)*2);
                bfr[2*np][0] = r0; bfr[2*np][1] = r1;
                bfr[2*np+1][0] = r2; bfr[2*np+1][1] = r3;
            }
#pragma unroll
            for (int mt = 0; mt < 4; mt++)
#pragma unroll
                for (int nt = 0; nt < NT; nt++)
                    MMA16816(acc[mt][nt][0], acc[mt][nt][1], acc[mt][nt][2], acc[mt][nt][3],
                             af[mt][0], af[mt][1], af[mt][2], af[mt][3],
                             bfr[nt][0], bfr[nt][1]);
        }
    }

    const int lr = lane >> 2, lc = (lane & 3) << 1;
#pragma unroll
    for (int mt = 0; mt < 4; mt++)
#pragma unroll
        for (int nt = 0; nt < NT; nt++) {
            int r0 = by*128 + wr*64 + mt*16 + lr;
            int c0 = bx*BN + wc*(BN/2) + nt*8 + lc;
            epi(z, r0,     c0,     acc[mt][nt][0]);
            epi(z, r0,     c0 + 1, acc[mt][nt][1]);
            epi(z, r0 + 8, c0,     acc[mt][nt][2]);
            epi(z, r0 + 8, c0 + 1, acc[mt][nt][3]);
        }
}

template<int BN, class Epi>
__global__ __launch_bounds__(128, 2)
void gemm_k(const bf16* __restrict__ A, const bf16* __restrict__ B, int K,
            size_t sA, size_t sB, Epi epi)
{
    const int z = blockIdx.z;
    const bf16* Ap = A + (size_t)z*sA + (size_t)blockIdx.y * 128 * K;
    const bf16* Bp = B + (size_t)z*sB + (size_t)blockIdx.x * BN  * K;
    gemm_core<BN, Epi>(Ap, Bp, K, z, blockIdx.y, blockIdx.x, epi);
}

__global__ __launch_bounds__(128, 2)
void qkv_k(const bf16* __restrict__ A,
           const bf16* __restrict__ Wq, const bf16* __restrict__ Wk,
           const bf16* __restrict__ Wv, EpiQKV epi)
{
    const int z = blockIdx.z;
    const bf16* W = (z == 0) ? Wq : (z == 1) ? Wk : Wv;
    const bf16* Ap = A + (size_t)blockIdx.y * 128 * KA_D;
    const bf16* Bp = W + (size_t)blockIdx.x * 128 * KA_D;
    gemm_core<128, EpiQKV>(Ap, Bp, KA_D, z, blockIdx.y, blockIdx.x, epi);
}

// ======================= weight transpose+split (B-layout) ==================
// W[K,N] fp32 -> out[N, 3K] bf16: [Wh | Wh | Wl]
__device__ __forceinline__ void wsplit_body(const float* __restrict__ W,
        bf16* __restrict__ out, int K, int N, int zmat, int bx, int by, int tid)
{
    __shared__ float t[32][33];
    const size_t mat  = (size_t)zmat * K * N;
    const size_t mato = (size_t)zmat * K * N * 3;
    const int n0 = bx*32, k0 = by*32;
    const int tx = tid & 31, ty = tid >> 5;
#pragma unroll
    for (int i = 0; i < 4; i++) {
        int k = k0 + ty*4 + i;
        t[ty*4+i][tx] = W[mat + (size_t)k*N + n0 + tx];
    }
    __syncthreads();
#pragma unroll
    for (int i = 0; i < 4; i++) {
        int n = n0 + ty*4 + i;
        float v = t[tx][ty*4+i];
        bf16 h, l; split2(v, h, l);
        size_t o = mato + (size_t)n*3*K + k0 + tx;
        out[o] = h; out[o + K] = h; out[o + 2*K] = l;
    }
}

__global__ __launch_bounds__(256) void wsplit_kernel(const float* __restrict__ W,
        bf16* __restrict__ out, int K, int N)
{
    wsplit_body(W, out, K, N, blockIdx.z, blockIdx.x, blockIdx.y, threadIdx.x);
}

// all 3 QKV weights in one launch: z = w*L + l, w in {0,1,2}
__global__ __launch_bounds__(256) void wsplit_qkv_kernel(
        const float* __restrict__ Wq, const float* __restrict__ Wk,
        const float* __restrict__ Wv,
        bf16* __restrict__ oq, bf16* __restrict__ ok, bf16* __restrict__ ov)
{
    const int w = blockIdx.z / L_, l = blockIdx.z % L_;
    const float* W = (w == 0) ? Wq : (w == 1) ? Wk : Wv;
    bf16* out = (w == 0) ? oq : (w == 1) ? ok : ov;
    wsplit_body(W, out, D_, D_, l, blockIdx.x, blockIdx.y, threadIdx.x);
}

// ======================= softmax (fp32 in -> aug bf16 out) ==================
__global__ __launch_bounds__(256) void softmax_split_kernel()
{
    const size_t base = (size_t)blockIdx.x * S_;
    const int tid = threadIdx.x;
    float x[4];
    float mx = -1e30f;
#pragma unroll
    for (int i = 0; i < 4; i++) {
        x[i] = g_sc[base + tid + i*256];
        mx = fmaxf(mx, x[i]);
    }
#pragma unroll
    for (int off = 16; off; off >>= 1)
        mx = fmaxf(mx, __shfl_xor_sync(0xffffffffu, mx, off));
    __shared__ float red[8];
    if ((tid & 31) == 0) red[tid >> 5] = mx;
    __syncthreads();
    if (tid == 0) {
        float v = red[0];
#pragma unroll
        for (int i = 1; i < 8; i++) v = fmaxf(v, red[i]);
        red[0] = v;
    }
    __syncthreads();
    mx = red[0];
    __syncthreads();
    float sum = 0.f;
#pragma unroll
    for (int i = 0; i < 4; i++) { x[i] = expf(x[i] - mx); sum += x[i]; }
#pragma unroll
    for (int off = 16; off; off >>= 1)
        sum += __shfl_xor_sync(0xffffffffu, sum, off);
    if ((tid & 31) == 0) red[tid >> 5] = sum;
    __syncthreads();
    if (tid == 0) {
        float v = 0.f;
#pragma unroll
        for (int i = 0; i < 8; i++) v += red[i];
        red[0] = 1.0f / v;
    }
    __syncthreads();
    const float inv = red[0];
    const size_t ob = (size_t)blockIdx.x * KA_D;
#pragma unroll
    for (int i = 0; i < 4; i++) {
        int idx = tid + i*256;
        float p = x[i] * inv;
        bf16 h, l; split2(p, h, l);
        g_pa[ob + idx] = h; g_pa[ob + S_ + idx] = l; g_pa[ob + 2*S_ + idx] = h;
    }
}

// ======================= LayerNorm (fp32 h + aug split out) =================
__device__ __forceinline__ void ln_stats(float s, float ss, float& mean, float& rstd)
{
#pragma unroll
    for (int off = 16; off; off >>= 1) {
        s  += __shfl_xor_sync(0xffffffffu, s,  off);
        ss += __shfl_xor_sync(0xffffffffu, ss, off);
    }
    __shared__ float rs[8], rss[8];
    const int w = threadIdx.x >> 5;
    if ((threadIdx.x & 31) == 0) { rs[w] = s; rss[w] = ss; }
    __syncthreads();
    if (threadIdx.x == 0) {
        float a = 0.f, bb = 0.f;
#pragma unroll
        for (int i = 0; i < 8; i++) { a += rs[i]; bb += rss[i]; }
        float mu  = a * (1.0f / 1024.0f);
        float var = bb * (1.0f / 1024.0f) - mu * mu;
        rs[0]  = mu;
        rss[0] = rsqrtf(var + 1e-5f);
    }
    __syncthreads();
    mean = rs[0];
    rstd = rss[0];
}

__device__ __forceinline__ void write_act(size_t row, int idx, float y)
{
    g_h[row*D_ + idx] = y;
    bf16 h, l; split2(y, h, l);
    size_t b3 = row*KA_D + idx;
    g_aa[b3] = h; g_aa[b3 + D_] = l; g_aa[b3 + 2*D_] = h;
}

__global__ __launch_bounds__(256) void embed_ln_kernel(const int* __restrict__ ids,
                                                       const float* __restrict__ tok,
                                                       const float* __restrict__ pos,
                                                       const float* __restrict__ g,
                                                       const float* __restrict__ be)
{
    const int row  = blockIdx.x;
    const int spos = row & (S_ - 1);
    const size_t tbase = (size_t)ids[row] * D_;
    const size_t pbase = (size_t)spos * D_;
    float x[4]; float s = 0.f, ss = 0.f;
#pragma unroll
    for (int i = 0; i < 4; i++) {
        int idx = threadIdx.x + i*256;
        x[i] = tok[tbase + idx] + pos[pbase + idx];
        s += x[i]; ss += x[i]*x[i];
    }
    float mean, rstd;
    ln_stats(s, ss, mean, rstd);
#pragma unroll
    for (int i = 0; i < 4; i++) {
        int idx = threadIdx.x + i*256;
        write_act(row, idx, (x[i] - mean) * rstd * g[idx] + be[idx]);
    }
}

__global__ __launch_bounds__(256) void add_ln_kernel(const float* __restrict__ g,
                                                     const float* __restrict__ be)
{
    const size_t base = (size_t)blockIdx.x * D_;
    float x[4]; float s = 0.f, ss = 0.f;
#pragma unroll
    for (int i = 0; i < 4; i++) {
        int idx = threadIdx.x + i*256;
        x[i] = g_h[base + idx] + g_ctx[base + idx];
        s += x[i]; ss += x[i]*x[i];
    }
    float mean, rstd;
    ln_stats(s, ss, mean, rstd);
#pragma unroll
    for (int i = 0; i < 4; i++) {
        int idx = threadIdx.x + i*256;
        write_act(blockIdx.x, idx, (x[i] - mean) * rstd * g[idx] + be[idx]);
    }
}

// ======================= driver =============================================
#define SMEM128 (4*(128*40 + 128*40)*2)   // 81920
#define SMEM64  (4*(128*40 +  64*40)*2)   // 61440

extern "C" void kernel_launch(void* const* d_in, const int* in_sizes, int n_in,
                              void* d_out, int out_size)
{
    (void)in_sizes; (void)n_in; (void)out_size;
    const int*   ids  = (const int*)  d_in[0];
    const float* mask = (const float*)d_in[1];
    const float* tok  = (const float*)d_in[2];
    const float* pos  = (const float*)d_in[3];
    const float* ln0g = (const float*)d_in[4];
    const float* ln0b = (const float*)d_in[5];
    const float* Wq   = (const float*)d_in[6];
    const float* bq   = (const float*)d_in[7];
    const float* Wk   = (const float*)d_in[8];
    const float* bk   = (const float*)d_in[9];
    const float* Wv   = (const float*)d_in[10];
    const float* bv   = (const float*)d_in[11];
    const float* ln1g = (const float*)d_in[12];
    const float* ln1b = (const float*)d_in[13];
    const float* W1   = (const float*)d_in[14];
    const float* b1   = (const float*)d_in[15];
    const float* W2   = (const float*)d_in[16];
    const float* b2   = (const float*)d_in[17];
    const float* ln2g = (const float*)d_in[18];
    const float* ln2b = (const float*)d_in[19];
    const float* Wlm  = (const float*)d_in[20];

    cudaFuncSetAttribute(qkv_k, cudaFuncAttributeMaxDynamicSharedMemorySize, SMEM128);
    cudaFuncSetAttribute(gemm_k<128, EpiScore>, cudaFuncAttributeMaxDynamicSharedMemorySize, SMEM128);
    cudaFuncSetAttribute(gemm_k<128, EpiGelu>,  cudaFuncAttributeMaxDynamicSharedMemorySize, SMEM128);
    cudaFuncSetAttribute(gemm_k<128, EpiF32>,   cudaFuncAttributeMaxDynamicSharedMemorySize, SMEM128);
    cudaFuncSetAttribute(gemm_k<64,  EpiF32>,   cudaFuncAttributeMaxDynamicSharedMemorySize, SMEM64);
    cudaFuncSetAttribute(gemm_k<64,  EpiCtx>,   cudaFuncAttributeMaxDynamicSharedMemorySize, SMEM64);

    bf16 *wq, *wk, *wv, *w1, *w2, *wlm, *aa, *qa, *ka, *va, *ffa, *pa;
    float *ctxp;
    cudaGetSymbolAddress((void**)&wq,  g_wq);
    cudaGetSymbolAddress((void**)&wk,  g_wk);
    cudaGetSymbolAddress((void**)&wv,  g_wv);
    cudaGetSymbolAddress((void**)&w1,  g_w1);
    cudaGetSymbolAddress((void**)&w2,  g_w2);
    cudaGetSymbolAddress((void**)&wlm, g_wlm);
    cudaGetSymbolAddress((void**)&aa,  g_aa);
    cudaGetSymbolAddress((void**)&qa,  g_qa);
    cudaGetSymbolAddress((void**)&ka,  g_ka);
    cudaGetSymbolAddress((void**)&va,  g_va);
    cudaGetSymbolAddress((void**)&ffa, g_ffa);
    cudaGetSymbolAddress((void**)&pa,  g_pa);
    cudaGetSymbolAddress((void**)&ctxp, g_ctx);

    // Prologue: 3 wsplits + embed (4 launches), so the early ncu capture slots
    // land on real GEMMs (launch 5 = qkv_k, launch 6 = score GEMM).
    // The Wlm wsplit is deferred to just before the LM head (its only consumer).
    wsplit_qkv_kernel<<<dim3(D_/32, D_/32, 3*L_), 256>>>(Wq, Wk, Wv, wq, wk, wv);
    wsplit_kernel<<<dim3(FF_/32, D_/32,  L_), 256>>>(W1,  w1,  D_,  FF_);
    wsplit_kernel<<<dim3(D_/32,  FF_/32, L_), 256>>>(W2,  w2,  FF_, D_);

    embed_ln_kernel<<<ROWS_, 256>>>(ids, tok, pos, ln0g, ln0b);

    const size_t WDD = (size_t)D_*KA_D;
    const size_t W1S = (size_t)FF_*KA_D;
    const size_t W2S = (size_t)D_*KA_FF;

    for (int l = 0; l < L_; l++) {
        qkv_k<<<dim3(D_/128, ROWS_/128, 3), 128, SMEM128>>>(
            aa, wq + l*WDD, wk + l*WDD, wv + l*WDD,
            EpiQKV{bq + (size_t)l*D_, bk + (size_t)l*D_, bv + (size_t)l*D_});

        gemm_k<128, EpiScore><<<dim3(S_/128, S_/128, B_*H_), 128, SMEM128>>>(
            qa, ka, KA_DH, (size_t)S_*KA_DH, (size_t)S_*KA_DH, EpiScore{mask});
        softmax_split_kernel<<<B_*H_*S_, 256>>>();
        gemm_k<64, EpiCtx><<<dim3(1, S_/128, B_*H_), 128, SMEM64>>>(
            pa, va, KA_D, (size_t)S_*KA_D, (size_t)DH_*KA_D, EpiCtx{});

        add_ln_kernel<<<ROWS_, 256>>>(ln1g + (size_t)l*D_, ln1b + (size_t)l*D_);

        gemm_k<128, EpiGelu><<<dim3(FF_/128, ROWS_/128, 1), 128, SMEM128>>>(
            aa, w1 + l*W1S, KA_D, 0, 0, EpiGelu{b1 + (size_t)l*FF_});
        gemm_k<64, EpiF32><<<dim3(D_/64, ROWS_/128, 1), 128, SMEM64>>>(
            ffa, w2 + l*W2S, KA_FF, 0, 0, EpiF32{ctxp, b2 + (size_t)l*D_, D_});

        add_ln_kernel<<<ROWS_, 256>>>(ln2g + (size_t)l*D_, ln2b + (size_t)l*D_);
    }

    wsplit_kernel<<<dim3(V_/32, D_/32, 1), 256>>>(Wlm, wlm, D_, V_);
    gemm_k<128, EpiF32><<<dim3(V_/128, ROWS_/128, 1), 128, SMEM128>>>(
        aa, wlm, KA_D, 0, 0, EpiF32{(float*)d_out, nullptr, V_});
}